// round 2
// baseline (speedup 1.0000x reference)
#include <cuda_runtime.h>

#define LN_EPS 1e-5f

// Problem constants (CoevolExtractor: B=1, N=128, L=256, P=32, n_out=128)
#define DEPTH_N 128
#define SEQ_L   256
#define PDIM    32
#define KDIM    1024   // P*P
#define NOUT    128

// Scratch (device globals: no allocations allowed in kernel_launch)
__device__ float g_gW[KDIM * NOUT];  // [k][o] = gamma[k] * W[o][k]
__device__ float g_cb[NOUT];         // b[o] + sum_k beta[k]*W[o][k]

// ---------------------------------------------------------------------------
// Prep: fold gamma into W (transposed to [k][o] for coalesced GEMM2 reads),
// fold beta/bias into a per-output constant.
// ---------------------------------------------------------------------------
__global__ void prep_gw_kernel(const float* __restrict__ gamma,
                               const float* __restrict__ W) {
    const int k = blockIdx.x;
    const int o = threadIdx.x;
    g_gW[k * NOUT + o] = gamma[k] * W[o * KDIM + k];
}

__global__ void prep_cb_kernel(const float* __restrict__ beta,
                               const float* __restrict__ W,
                               const float* __restrict__ b) {
    const int o = threadIdx.x;
    float s = b[o];
    for (int k = 0; k < KDIM; ++k) s += beta[k] * W[o * KDIM + k];
    g_cb[o] = s;
}

// ---------------------------------------------------------------------------
// Fused kernel. One CTA = 4x4 tile of (i,l) pairs.  96 KB smem -> 2 CTAs/SM.
//  GEMM1: pairblk[128x128] = A_tile^T(128n x 128(i,j)) dot B_tile (K=128)
//         classic register tiling, 8x8 per thread, 256 threads. Thread layout
//         chosen so each 32x32 (i,l) block is owned by one half-warp
//         -> shuffle-only LN reduction.
//  LN:    per (i,l) pair over its 1024 values, in registers.
//  GEMM2: out[16 pairs x 128 o] = normpair[16x1024] dot gW[1024x128],
//         gW streamed through smem in 64-row chunks (gW is L2-resident:
//         512 KB read by all 4096 CTAs).
// ---------------------------------------------------------------------------
__global__ __launch_bounds__(256, 2)
void coevol_fused_kernel(const float* __restrict__ A,    // x_down   [n][i][j]
                         const float* __restrict__ Bm,   // x_down_w [n][l][m]
                         float* __restrict__ out) {      // [i][l][o]
    extern __shared__ float smem[];
    float* As = smem;           // [16][128] n-chunk of A tile (GEMM1 phase)
    float* Bs = smem + 2048;    // [16][128]
    float* Np = smem;           // [16][1024] normalized pair (reuses As/Bs)
    float* Ws = smem + 16384;   // [64][128] gW chunk (32 KB)

    const int tid = threadIdx.x;
    const int bx = blockIdx.x;  // i tile (4 i's)
    const int by = blockIdx.y;  // l tile (4 l's)

    // pair-block ownership: blk = which (ii,ll) of the 4x4; s = sub-position
    const int blk = tid >> 4;          // 0..15 ; ii = blk>>2, ll = blk&3
    const int s   = tid & 15;          // 16 threads per 32x32 block (half-warp)
    const int r0  = (blk >> 2) * 32 + (s >> 2) * 8;  // row in 128 (i,j axis)
    const int c0  = (blk & 3) * 32 + (s & 3) * 8;    // col in 128 (l,m axis)

    float acc[8][8];
#pragma unroll
    for (int u = 0; u < 8; ++u)
#pragma unroll
        for (int v = 0; v < 8; ++v) acc[u][v] = 0.f;

    const float4* A4 = (const float4*)A;
    const float4* B4 = (const float4*)Bm;
    float4* As4 = (float4*)As;
    float4* Bs4 = (float4*)Bs;

    // A[n, i0..i0+3, 0..31] is 128 contiguous floats at n*8192 + bx*128.
    for (int nc = 0; nc < DEPTH_N; nc += 16) {
#pragma unroll
        for (int it = 0; it < 2; ++it) {
            const int v = tid + it * 256;       // 0..511
            const int nn = v >> 5, c = v & 31;  // row, float4-col
            As4[v] = A4[(size_t)(nc + nn) * 2048 + bx * 32 + c];
            Bs4[v] = B4[(size_t)(nc + nn) * 2048 + by * 32 + c];
        }
        __syncthreads();
#pragma unroll
        for (int nn = 0; nn < 16; ++nn) {
            float a[8], bq[8];
            *(float4*)&a[0]  = *(const float4*)&As[nn * 128 + r0];
            *(float4*)&a[4]  = *(const float4*)&As[nn * 128 + r0 + 4];
            *(float4*)&bq[0] = *(const float4*)&Bs[nn * 128 + c0];
            *(float4*)&bq[4] = *(const float4*)&Bs[nn * 128 + c0 + 4];
#pragma unroll
            for (int u = 0; u < 8; ++u)
#pragma unroll
                for (int v = 0; v < 8; ++v)
                    acc[u][v] = fmaf(a[u], bq[v], acc[u][v]);
        }
        __syncthreads();
    }

    // ---- LayerNorm stats: reduce over the 16 lanes owning this block ----
    float sum = 0.f, sq = 0.f;
#pragma unroll
    for (int u = 0; u < 8; ++u)
#pragma unroll
        for (int v = 0; v < 8; ++v) {
            sum += acc[u][v];
            sq = fmaf(acc[u][v], acc[u][v], sq);
        }
#pragma unroll
    for (int off = 8; off >= 1; off >>= 1) {
        sum += __shfl_xor_sync(0xffffffffu, sum, off);
        sq  += __shfl_xor_sync(0xffffffffu, sq, off);
    }
    const float mean = sum * (1.f / KDIM);
    const float var  = sq * (1.f / KDIM) - mean * mean;
    const float rstd = rsqrtf(var + LN_EPS);

    // Store normalized pair: Np[blk][j*32 + m]  (gamma folded into gW)
    const int jb = (s >> 2) * 8, mb = (s & 3) * 8;
#pragma unroll
    for (int u = 0; u < 8; ++u)
#pragma unroll
        for (int v = 0; v < 8; ++v)
            Np[blk * KDIM + (jb + u) * 32 + (mb + v)] = (acc[u][v] - mean) * rstd;
    __syncthreads();

    // ---- GEMM2: out[p][o] = sum_k Np[p][k] * gW[k][o] ----
    const int o  = tid & 127;          // output channel
    const int p0 = (tid >> 7) * 8;     // 8 pairs per thread
    float oacc[8];
#pragma unroll
    for (int p = 0; p < 8; ++p) oacc[p] = 0.f;

    float4* Ws4 = (float4*)Ws;
    const float4* gW4 = (const float4*)g_gW;

    for (int kc = 0; kc < KDIM; kc += 64) {
        // load 64 x 128 gW chunk: 2048 float4 by 256 threads
#pragma unroll
        for (int it = 0; it < 8; ++it) {
            const int v = tid + it * 256;  // 0..2047 float4's
            Ws4[v] = gW4[kc * 32 + v];
        }
        __syncthreads();
#pragma unroll 4
        for (int k = 0; k < 64; k += 4) {
            float4 xv[8];
#pragma unroll
            for (int p = 0; p < 8; ++p)
                xv[p] = *(const float4*)&Np[(p0 + p) * KDIM + kc + k];
            const float w0 = Ws[(k + 0) * 128 + o];
            const float w1 = Ws[(k + 1) * 128 + o];
            const float w2 = Ws[(k + 2) * 128 + o];
            const float w3 = Ws[(k + 3) * 128 + o];
#pragma unroll
            for (int p = 0; p < 8; ++p) {
                oacc[p] = fmaf(xv[p].x, w0, oacc[p]);
                oacc[p] = fmaf(xv[p].y, w1, oacc[p]);
                oacc[p] = fmaf(xv[p].z, w2, oacc[p]);
                oacc[p] = fmaf(xv[p].w, w3, oacc[p]);
            }
        }
        __syncthreads();
    }

    const float cbv = g_cb[o];
#pragma unroll
    for (int p = 0; p < 8; ++p) {
        const int pg = p0 + p;
        const int gi = bx * 4 + (pg >> 2);
        const int gl = by * 4 + (pg & 3);
        out[((size_t)gi * SEQ_L + gl) * NOUT + o] = oacc[p] + cbv;
    }
}

// ---------------------------------------------------------------------------
extern "C" void kernel_launch(void* const* d_in, const int* in_sizes, int n_in,
                              void* d_out, int out_size) {
    const float* x_down   = (const float*)d_in[0];
    const float* x_down_w = (const float*)d_in[1];
    const float* gamma    = (const float*)d_in[2];
    const float* beta     = (const float*)d_in[3];
    const float* W        = (const float*)d_in[4];
    const float* b        = (const float*)d_in[5];
    float* out = (float*)d_out;

    // Opt-in for >48KB dynamic smem. Not a stream op; graph-capture safe.
    cudaFuncSetAttribute(coevol_fused_kernel,
                         cudaFuncAttributeMaxDynamicSharedMemorySize, 98304);

    prep_gw_kernel<<<KDIM, NOUT>>>(gamma, W);
    prep_cb_kernel<<<1, NOUT>>>(beta, W, b);

    dim3 grid(SEQ_L / 4, SEQ_L / 4);  // 64 x 64 CTAs
    coevol_fused_kernel<<<grid, 256, 98304>>>(x_down, x_down_w, out);
}

// round 3
// speedup vs baseline: 1.0450x; 1.0450x over previous
#include <cuda_runtime.h>

#define LN_EPS 1e-5f

// Problem constants (CoevolExtractor: B=1, N=128, L=256, P=32, n_out=128)
#define DEPTH_N 128
#define SEQ_L   256
#define PDIM    32
#define KDIM    1024   // P*P
#define NOUT    128

typedef unsigned long long u64;

// ---- packed f32x2 helpers (Blackwell FFMA2 path; only reachable via PTX) ----
__device__ __forceinline__ u64 pack2(float lo, float hi) {
    u64 r; asm("mov.b64 %0, {%1, %2};" : "=l"(r) : "f"(lo), "f"(hi)); return r;
}
__device__ __forceinline__ void unpack2(u64 x, float& lo, float& hi) {
    asm("mov.b64 {%0, %1}, %2;" : "=f"(lo), "=f"(hi) : "l"(x));
}
__device__ __forceinline__ void ffma2(u64& d, u64 a, u64 b) {
    asm("fma.rn.f32x2 %0, %1, %2, %0;" : "+l"(d) : "l"(a), "l"(b));
}
__device__ __forceinline__ u64 add2(u64 a, u64 b) {
    u64 r; asm("add.rn.f32x2 %0, %1, %2;" : "=l"(r) : "l"(a), "l"(b)); return r;
}
__device__ __forceinline__ u64 mul2(u64 a, u64 b) {
    u64 r; asm("mul.rn.f32x2 %0, %1, %2;" : "=l"(r) : "l"(a), "l"(b)); return r;
}

// Scratch (device globals: no allocations allowed in kernel_launch)
__device__ float g_gW[KDIM * NOUT];  // [k][o] = gamma[k] * W[o][k]
__device__ float g_cb[NOUT];         // b[o] + sum_k beta[k]*W[o][k]

// ---------------------------------------------------------------------------
// Prep (single kernel so the fused kernel lands on ncu's -s 5 launch index):
// blocks 0..KDIM-1: fold gamma into W (transposed [k][o]).
// block KDIM:       fold beta/bias into per-output constant.
// ---------------------------------------------------------------------------
__global__ void prep_kernel(const float* __restrict__ gamma,
                            const float* __restrict__ beta,
                            const float* __restrict__ W,
                            const float* __restrict__ b) {
    if (blockIdx.x < KDIM) {
        const int k = blockIdx.x;
        const int o = threadIdx.x;
        g_gW[k * NOUT + o] = gamma[k] * W[o * KDIM + k];
    } else {
        const int o = threadIdx.x;
        float s = b[o];
        for (int k = 0; k < KDIM; ++k) s += beta[k] * W[o * KDIM + k];
        g_cb[o] = s;
    }
}

// ---------------------------------------------------------------------------
// Fused kernel. One CTA = 4x4 tile of (i,l) pairs. 96 KB smem -> 2 CTAs/SM.
// All inner-loop math uses packed fma.rn.f32x2 (2 FMA/lane/inst).
// ---------------------------------------------------------------------------
__global__ __launch_bounds__(256, 2)
void coevol_fused_kernel(const float* __restrict__ A,    // x_down   [n][i][j]
                         const float* __restrict__ Bm,   // x_down_w [n][l][m]
                         float* __restrict__ out) {      // [i][l][o]
    extern __shared__ float smem[];
    float* As = smem;           // [16][128] n-chunk of A tile (GEMM1 phase)
    float* Bs = smem + 2048;    // [16][128]
    float* Np = smem;           // [16][1024] normalized pair (reuses As/Bs)
    float* Ws = smem + 16384;   // [64][128] gW chunk (32 KB)

    const int tid = threadIdx.x;
    const int bx = blockIdx.x;  // i tile (4 i's)
    const int by = blockIdx.y;  // l tile (4 l's)

    // pair-block ownership: blk = which (ii,ll) of the 4x4; s = sub-position
    const int blk = tid >> 4;          // 0..15 ; ii = blk>>2, ll = blk&3
    const int s   = tid & 15;          // 16 threads per 32x32 block (half-warp)
    const int r0  = (blk >> 2) * 32 + (s >> 2) * 8;  // row in 128 (i,j axis)
    const int c0  = (blk & 3) * 32 + (s & 3) * 8;    // col in 128 (l,m axis)

    // acc2[u][v2]: lanes (v=2*v2, v=2*v2+1)
    u64 acc2[8][4];
#pragma unroll
    for (int u = 0; u < 8; ++u)
#pragma unroll
        for (int v = 0; v < 4; ++v) acc2[u][v] = 0ull;

    const float4* A4 = (const float4*)A;
    const float4* B4 = (const float4*)Bm;
    float4* As4 = (float4*)As;
    float4* Bs4 = (float4*)Bs;

    // A[n, i0..i0+3, 0..31] is 128 contiguous floats at n*8192 + bx*128.
    for (int nc = 0; nc < DEPTH_N; nc += 16) {
#pragma unroll
        for (int it = 0; it < 2; ++it) {
            const int v = tid + it * 256;       // 0..511
            const int nn = v >> 5, c = v & 31;  // row, float4-col
            As4[v] = A4[(size_t)(nc + nn) * 2048 + bx * 32 + c];
            Bs4[v] = B4[(size_t)(nc + nn) * 2048 + by * 32 + c];
        }
        __syncthreads();
#pragma unroll
        for (int nn = 0; nn < 16; ++nn) {
            float a[8];
            u64 av2[8], bq2[4];
            *(float4*)&a[0] = *(const float4*)&As[nn * 128 + r0];
            *(float4*)&a[4] = *(const float4*)&As[nn * 128 + r0 + 4];
            const u64* brow = (const u64*)&Bs[nn * 128 + c0];  // 32B aligned
#pragma unroll
            for (int v = 0; v < 4; ++v) bq2[v] = brow[v];
#pragma unroll
            for (int u = 0; u < 8; ++u) av2[u] = pack2(a[u], a[u]);
#pragma unroll
            for (int u = 0; u < 8; ++u)
#pragma unroll
                for (int v = 0; v < 4; ++v)
                    ffma2(acc2[u][v], av2[u], bq2[v]);
        }
        __syncthreads();
    }

    // ---- LayerNorm stats (packed) + half-warp shuffle reduction ----
    u64 sum2 = 0ull, sq2 = 0ull;
#pragma unroll
    for (int u = 0; u < 8; ++u)
#pragma unroll
        for (int v = 0; v < 4; ++v) {
            sum2 = add2(sum2, acc2[u][v]);
            ffma2(sq2, acc2[u][v], acc2[u][v]);
        }
    float slo, shi, qlo, qhi;
    unpack2(sum2, slo, shi);
    unpack2(sq2, qlo, qhi);
    float sum = slo + shi, sq = qlo + qhi;
#pragma unroll
    for (int off = 8; off >= 1; off >>= 1) {
        sum += __shfl_xor_sync(0xffffffffu, sum, off);
        sq  += __shfl_xor_sync(0xffffffffu, sq, off);
    }
    const float mean = sum * (1.f / KDIM);
    const float var  = sq * (1.f / KDIM) - mean * mean;
    const float rstd = rsqrtf(var + LN_EPS);
    const u64 nmean2 = pack2(-mean, -mean);
    const u64 rstd2  = pack2(rstd, rstd);

    // Store normalized pair: Np[blk][j*32 + m]  (gamma folded into gW)
    const int jb = (s >> 2) * 8, mb = (s & 3) * 8;
#pragma unroll
    for (int u = 0; u < 8; ++u) {
        u64* nprow = (u64*)&Np[blk * KDIM + (jb + u) * 32 + mb];  // 8B aligned
#pragma unroll
        for (int v = 0; v < 4; ++v)
            nprow[v] = mul2(add2(acc2[u][v], nmean2), rstd2);
    }
    __syncthreads();

    // ---- GEMM2: out[p][o] = sum_k Np[p][k] * gW[k][o], packed over k ----
    const int o  = tid & 127;          // output channel
    const int p0 = (tid >> 7) * 8;     // 8 pairs per thread
    u64 oacc2[8];                      // lanes = (even-k, odd-k) partials
#pragma unroll
    for (int p = 0; p < 8; ++p) oacc2[p] = 0ull;

    float4* Ws4 = (float4*)Ws;
    const float4* gW4 = (const float4*)g_gW;

    for (int kc = 0; kc < KDIM; kc += 64) {
        // load 64 x 128 gW chunk: 2048 float4 by 256 threads
#pragma unroll
        for (int it = 0; it < 8; ++it) {
            const int v = tid + it * 256;  // 0..2047 float4's
            Ws4[v] = gW4[kc * 32 + v];
        }
        __syncthreads();
#pragma unroll 4
        for (int k = 0; k < 64; k += 4) {
            const u64 w01 = pack2(Ws[(k + 0) * 128 + o], Ws[(k + 1) * 128 + o]);
            const u64 w23 = pack2(Ws[(k + 2) * 128 + o], Ws[(k + 3) * 128 + o]);
#pragma unroll
            for (int p = 0; p < 8; ++p) {
                // 16B-aligned: kc+k is a multiple of 4 floats
                const ulonglong2 xq =
                    *(const ulonglong2*)&Np[(p0 + p) * KDIM + kc + k];
                ffma2(oacc2[p], xq.x, w01);
                ffma2(oacc2[p], xq.y, w23);
            }
        }
        __syncthreads();
    }

    const float cbv = g_cb[o];
#pragma unroll
    for (int p = 0; p < 8; ++p) {
        float lo, hi;
        unpack2(oacc2[p], lo, hi);
        const int pg = p0 + p;
        const int gi = bx * 4 + (pg >> 2);
        const int gl = by * 4 + (pg & 3);
        out[((size_t)gi * SEQ_L + gl) * NOUT + o] = lo + hi + cbv;
    }
}

// ---------------------------------------------------------------------------
extern "C" void kernel_launch(void* const* d_in, const int* in_sizes, int n_in,
                              void* d_out, int out_size) {
    const float* x_down   = (const float*)d_in[0];
    const float* x_down_w = (const float*)d_in[1];
    const float* gamma    = (const float*)d_in[2];
    const float* beta     = (const float*)d_in[3];
    const float* W        = (const float*)d_in[4];
    const float* b        = (const float*)d_in[5];
    float* out = (float*)d_out;

    // Opt-in for >48KB dynamic smem. Not a stream op; graph-capture safe.
    cudaFuncSetAttribute(coevol_fused_kernel,
                         cudaFuncAttributeMaxDynamicSharedMemorySize, 98304);

    prep_kernel<<<KDIM + 1, NOUT>>>(gamma, beta, W, b);

    dim3 grid(SEQ_L / 4, SEQ_L / 4);  // 64 x 64 CTAs
    coevol_fused_kernel<<<grid, 256, 98304>>>(x_down, x_down_w, out);
}

// round 5
// speedup vs baseline: 2.2368x; 2.1405x over previous
#include <cuda_runtime.h>
#include <cuda_bf16.h>
#include <cstdint>

#define LN_EPS 1e-5f
#define SEQ_L  256
#define KDIM   1024
#define NOUT   128

// ---------------- global scratch (no allocs allowed) ----------------
__device__ __align__(16) __nv_bfloat16 g_Ah[128 * 8192];  // x_down   hi [n][ij]
__device__ __align__(16) __nv_bfloat16 g_Al[128 * 8192];
__device__ __align__(16) __nv_bfloat16 g_Bh[128 * 8192];  // x_down_w hi [n][lm]
__device__ __align__(16) __nv_bfloat16 g_Bl[128 * 8192];
__device__ __align__(16) __nv_bfloat16 g_gWh[NOUT * KDIM];  // gamma*W hi [o][k]
__device__ __align__(16) __nv_bfloat16 g_gWl[NOUT * KDIM];
__device__ float g_cb[NOUT];

// ---------------- smem layout (bytes) ----------------
// phase1: 4 buffers [64 n][136 bf16 pitch] = 17408 B each
#define OFF_AH 0
#define OFF_AL 17408
#define OFF_BH 34816
#define OFF_BL 52224
// phase2: Np hi/lo [16 p][516 b32 pitch] = 33024 B each; gW chunk [128][144B] x2
#define OFF_NPH 0
#define OFF_NPL 33024
#define OFF_GWH 66048
#define OFF_GWL 84480
#define SMEM_TOTAL 102912

__device__ __forceinline__ uint32_t smem_u32(const void* p) {
    uint32_t a;
    asm("{ .reg .u64 t; cvta.to.shared.u64 t, %1; cvt.u32.u64 %0, t; }"
        : "=r"(a) : "l"(p));
    return a;
}
__device__ __forceinline__ void ldmx4t(uint32_t* r, uint32_t addr) {
    asm volatile("ldmatrix.sync.aligned.m8n8.x4.trans.shared.b16 {%0,%1,%2,%3}, [%4];"
                 : "=r"(r[0]), "=r"(r[1]), "=r"(r[2]), "=r"(r[3]) : "r"(addr));
}
__device__ __forceinline__ void ldmx2t(uint32_t* r, uint32_t addr) {
    asm volatile("ldmatrix.sync.aligned.m8n8.x2.trans.shared.b16 {%0,%1}, [%2];"
                 : "=r"(r[0]), "=r"(r[1]) : "r"(addr));
}
__device__ __forceinline__ void mma16816(float* c, const uint32_t* a, const uint32_t* b) {
    asm volatile(
        "mma.sync.aligned.m16n8k16.row.col.f32.bf16.bf16.f32 "
        "{%0,%1,%2,%3}, {%4,%5,%6,%7}, {%8,%9}, {%0,%1,%2,%3};"
        : "+f"(c[0]), "+f"(c[1]), "+f"(c[2]), "+f"(c[3])
        : "r"(a[0]), "r"(a[1]), "r"(a[2]), "r"(a[3]), "r"(b[0]), "r"(b[1]));
}

// ---------------- prep: fp32 -> bf16 hi/lo ----------------
__global__ void prep_conv(const float* __restrict__ A, const float* __restrict__ B) {
    const unsigned v = blockIdx.x * blockDim.x + threadIdx.x;  // 0..524287 (f4)
    const float4* src;
    __nv_bfloat16 *dh, *dl;
    unsigned i;
    if (v < 262144) { src = (const float4*)A; i = v; dh = g_Ah; dl = g_Al; }
    else            { src = (const float4*)B; i = v - 262144; dh = g_Bh; dl = g_Bl; }
    const float4 x = src[i];
    __nv_bfloat162 h01 = __floats2bfloat162_rn(x.x, x.y);
    __nv_bfloat162 h23 = __floats2bfloat162_rn(x.z, x.w);
    __nv_bfloat162 l01 = __floats2bfloat162_rn(x.x - __low2float(h01), x.y - __high2float(h01));
    __nv_bfloat162 l23 = __floats2bfloat162_rn(x.z - __low2float(h23), x.w - __high2float(h23));
    ((uint2*)dh)[i] = make_uint2(*(uint32_t*)&h01, *(uint32_t*)&h23);
    ((uint2*)dl)[i] = make_uint2(*(uint32_t*)&l01, *(uint32_t*)&l23);
}

__global__ void prep_w(const float* __restrict__ gamma, const float* __restrict__ beta,
                       const float* __restrict__ W, const float* __restrict__ b) {
    const int o = blockIdx.x;          // 128 blocks
    const int t = threadIdx.x;         // 256 threads
    float s = 0.f;
    for (int k = t; k < KDIM; k += 256) {
        const float wv = W[o * KDIM + k];
        const float gv = gamma[k] * wv;
        const __nv_bfloat16 h = __float2bfloat16(gv);
        g_gWh[o * KDIM + k] = h;
        g_gWl[o * KDIM + k] = __float2bfloat16(gv - __bfloat162float(h));
        s += beta[k] * wv;
    }
    __shared__ float red[256];
    red[t] = s;
    __syncthreads();
    for (int st = 128; st > 0; st >>= 1) {
        if (t < st) red[t] += red[t + st];
        __syncthreads();
    }
    if (t == 0) g_cb[o] = b[o] + red[0];
}

// ---------------- fused mma.sync kernel ----------------
__global__ __launch_bounds__(256, 2)
void coevol_mma_kernel(float* __restrict__ out) {
    extern __shared__ char sm[];
    const uint32_t SB = smem_u32(sm);

    const int tid = threadIdx.x;
    const int lane = tid & 31, w = tid >> 5;
    const int bx = blockIdx.x, by = blockIdx.y;

    // ---------------- GEMM1: D1[128 ij x 128 lm], K = 128 n ----------------
    const int mbase = (w & 3) * 32;     // ij tile base
    const int nbase = (w >> 2) * 64;    // lm tile base
    float acc[2][8][4];
#pragma unroll
    for (int mt = 0; mt < 2; ++mt)
#pragma unroll
        for (int nt = 0; nt < 8; ++nt)
#pragma unroll
            for (int c = 0; c < 4; ++c) acc[mt][nt][c] = 0.f;

    const int g4 = lane >> 3;           // ldmatrix lane group
    const int grow = lane & 7;
    const int kadd4 = (g4 >> 1) * 8, madd4 = (g4 & 1) * 8;   // x4 tile offsets
    const int kadd2 = (g4 & 1) * 8;                          // x2 tile offsets

    for (int nh = 0; nh < 2; ++nh) {
        // copy 4 buffers: [64 n][128 bf16] -> pitch 136 bf16 (272 B)
#pragma unroll
        for (int it = 0; it < 4; ++it) {
            const int v = it * 256 + tid;          // 0..1023
            const int r = v >> 4, c = v & 15;
            const unsigned srcA = (unsigned)(nh * 64 + r) * 1024u + (unsigned)bx * 16u + c;
            const unsigned srcB = (unsigned)(nh * 64 + r) * 1024u + (unsigned)by * 16u + c;
            const unsigned dst = (unsigned)r * 272u + (unsigned)c * 16u;
            *(uint4*)(sm + OFF_AH + dst) = ((const uint4*)g_Ah)[srcA];
            *(uint4*)(sm + OFF_AL + dst) = ((const uint4*)g_Al)[srcA];
            *(uint4*)(sm + OFF_BH + dst) = ((const uint4*)g_Bh)[srcB];
            *(uint4*)(sm + OFF_BL + dst) = ((const uint4*)g_Bl)[srcB];
        }
        __syncthreads();

#pragma unroll
        for (int ks = 0; ks < 4; ++ks) {
            uint32_t ah[2][4], al[2][4];
#pragma unroll
            for (int mt = 0; mt < 2; ++mt) {
                const uint32_t aoff = (uint32_t)(ks * 16 + kadd4 + grow) * 272u
                                    + (uint32_t)(mbase + mt * 16 + madd4) * 2u;
                ldmx4t(ah[mt], SB + OFF_AH + aoff);
                ldmx4t(al[mt], SB + OFF_AL + aoff);
            }
#pragma unroll
            for (int nt = 0; nt < 8; ++nt) {
                uint32_t bh[2], bl[2];
                const uint32_t boff = (uint32_t)(ks * 16 + kadd2 + grow) * 272u
                                    + (uint32_t)(nbase + nt * 8) * 2u;
                ldmx2t(bh, SB + OFF_BH + boff);
                ldmx2t(bl, SB + OFF_BL + boff);
#pragma unroll
                for (int mt = 0; mt < 2; ++mt) {
                    mma16816(acc[mt][nt], ah[mt], bh);
                    mma16816(acc[mt][nt], ah[mt], bl);
                    mma16816(acc[mt][nt], al[mt], bh);
                }
            }
        }
        __syncthreads();
    }

    // ---------------- LayerNorm (warp-local) -> Np bf16 hi/lo ----------------
    const int i_loc = w & 3;
#pragma unroll
    for (int lb = 0; lb < 2; ++lb) {
        const int l_loc = (w >> 2) * 2 + lb;
        float sum = 0.f, sq = 0.f;
#pragma unroll
        for (int mt = 0; mt < 2; ++mt)
#pragma unroll
            for (int nt4 = 0; nt4 < 4; ++nt4)
#pragma unroll
                for (int c = 0; c < 4; ++c) {
                    const float v = acc[mt][lb * 4 + nt4][c];
                    sum += v;
                    sq = fmaf(v, v, sq);
                }
#pragma unroll
        for (int off = 16; off >= 1; off >>= 1) {
            sum += __shfl_xor_sync(0xffffffffu, sum, off);
            sq  += __shfl_xor_sync(0xffffffffu, sq, off);
        }
        const float mean = sum * (1.f / KDIM);
        const float var  = sq * (1.f / KDIM) - mean * mean;
        const float rstd = rsqrtf(var + LN_EPS);
        const int p = i_loc * 4 + l_loc;
#pragma unroll
        for (int mt = 0; mt < 2; ++mt)
#pragma unroll
            for (int nt4 = 0; nt4 < 4; ++nt4)
#pragma unroll
                for (int cp = 0; cp < 2; ++cp) {
                    const float f0 = (acc[mt][lb * 4 + nt4][cp * 2 + 0] - mean) * rstd;
                    const float f1 = (acc[mt][lb * 4 + nt4][cp * 2 + 1] - mean) * rstd;
                    __nv_bfloat162 h2 = __floats2bfloat162_rn(f0, f1);
                    __nv_bfloat162 l2 = __floats2bfloat162_rn(f0 - __low2float(h2),
                                                              f1 - __high2float(h2));
                    const int j  = mt * 16 + (lane >> 2) + cp * 8;
                    const int mc = nt4 * 4 + (lane & 3);
                    const int idx = p * 516 + j * 16 + (mc ^ ((j & 3) << 2));
                    *(uint32_t*)(sm + OFF_NPH + idx * 4) = *(uint32_t*)&h2;
                    *(uint32_t*)(sm + OFF_NPL + idx * 4) = *(uint32_t*)&l2;
                }
    }
    __syncthreads();

    // ---------------- GEMM2: D2[16 p x 128 o], K = 1024 ----------------
    const int ob = w * 16;
    float acc2[2][4];
#pragma unroll
    for (int nt = 0; nt < 2; ++nt)
#pragma unroll
        for (int c = 0; c < 4; ++c) acc2[nt][c] = 0.f;

    for (int ch = 0; ch < 16; ++ch) {
        // copy gW chunk hi+lo: [128 o][64 k] -> pitch 72 bf16 (144 B)
#pragma unroll
        for (int it = 0; it < 8; ++it) {
            const int v = it * 256 + tid;          // 0..2047
            const int r = (v >> 3) & 127, cc = v & 7;
            const unsigned src = (unsigned)r * 128u + (unsigned)ch * 8u + cc;
            const unsigned dst = (unsigned)r * 144u + (unsigned)cc * 16u;
            if (v < 1024) *(uint4*)(sm + OFF_GWH + dst) = ((const uint4*)g_gWh)[src];
            else          *(uint4*)(sm + OFF_GWL + dst) = ((const uint4*)g_gWl)[src];
        }
        __syncthreads();

#pragma unroll
        for (int ks = 0; ks < 4; ++ks) {
            // Np A fragment (manual conflict-free LDS, swizzled)
            const int Kb = ch * 32 + ks * 8 + (lane & 3);
            const int j  = Kb >> 4;
            const int mc = Kb & 15;
            const int sw0 = mc ^ ((j & 3) << 2);
            const int sw2 = (mc + 4) ^ ((j & 3) << 2);
            const int r0 = (lane >> 2) * 516 + j * 16;
            uint32_t ah[4], al[4];
            ah[0] = *(const uint32_t*)(sm + OFF_NPH + (r0 + sw0) * 4);
            ah[1] = *(const uint32_t*)(sm + OFF_NPH + (r0 + 8 * 516 + sw0) * 4);
            ah[2] = *(const uint32_t*)(sm + OFF_NPH + (r0 + sw2) * 4);
            ah[3] = *(const uint32_t*)(sm + OFF_NPH + (r0 + 8 * 516 + sw2) * 4);
            al[0] = *(const uint32_t*)(sm + OFF_NPL + (r0 + sw0) * 4);
            al[1] = *(const uint32_t*)(sm + OFF_NPL + (r0 + 8 * 516 + sw0) * 4);
            al[2] = *(const uint32_t*)(sm + OFF_NPL + (r0 + sw2) * 4);
            al[3] = *(const uint32_t*)(sm + OFF_NPL + (r0 + 8 * 516 + sw2) * 4);
#pragma unroll
            for (int nt = 0; nt < 2; ++nt) {
                const int o = ob + nt * 8 + (lane >> 2);
                const int kb = ks * 8 + (lane & 3);
                uint32_t bh[2], bl[2];
                bh[0] = *(const uint32_t*)(sm + OFF_GWH + (o * 36 + kb) * 4);
                bh[1] = *(const uint32_t*)(sm + OFF_GWH + (o * 36 + kb + 4) * 4);
                bl[0] = *(const uint32_t*)(sm + OFF_GWL + (o * 36 + kb) * 4);
                bl[1] = *(const uint32_t*)(sm + OFF_GWL + (o * 36 + kb + 4) * 4);
                mma16816(acc2[nt], ah, bh);
                mma16816(acc2[nt], ah, bl);
                mma16816(acc2[nt], al, bh);
            }
        }
        __syncthreads();
    }

    // ---------------- Epilogue ----------------
#pragma unroll
    for (int nt = 0; nt < 2; ++nt) {
        const int o0 = ob + nt * 8 + (lane & 3) * 2;
        const float cb0 = g_cb[o0], cb1 = g_cb[o0 + 1];
#pragma unroll
        for (int half = 0; half < 2; ++half) {
            const int p = (lane >> 2) + half * 8;
            const int gi = bx * 4 + (p >> 2);
            const int gl = by * 4 + (p & 3);
            float2 val;
            val.x = acc2[nt][half * 2 + 0] + cb0;
            val.y = acc2[nt][half * 2 + 1] + cb1;
            *(float2*)&out[((size_t)gi * SEQ_L + gl) * NOUT + o0] = val;
        }
    }
}

// ---------------------------------------------------------------------------
extern "C" void kernel_launch(void* const* d_in, const int* in_sizes, int n_in,
                              void* d_out, int out_size) {
    const float* x_down   = (const float*)d_in[0];
    const float* x_down_w = (const float*)d_in[1];
    const float* gamma    = (const float*)d_in[2];
    const float* beta     = (const float*)d_in[3];
    const float* W        = (const float*)d_in[4];
    const float* b        = (const float*)d_in[5];
    float* out = (float*)d_out;

    cudaFuncSetAttribute(coevol_mma_kernel,
                         cudaFuncAttributeMaxDynamicSharedMemorySize, SMEM_TOTAL);

    prep_conv<<<2048, 256>>>(x_down, x_down_w);
    prep_w<<<NOUT, 256>>>(gamma, beta, W, b);

    dim3 grid(SEQ_L / 4, SEQ_L / 4);  // 64 x 64
    coevol_mma_kernel<<<grid, 256, SMEM_TOTAL>>>(out);
}

// round 7
// speedup vs baseline: 3.0275x; 1.3535x over previous
#include <cuda_runtime.h>
#include <cuda_bf16.h>
#include <cstdint>

#define LN_EPS 1e-5f
#define SEQ_L  256
#define KDIM   1024
#define NOUT   128

// ---------------- global scratch (no allocs allowed) ----------------
__device__ __align__(16) __nv_bfloat16 g_Ah[128 * 8192];  // x_down   hi [n][ij]
__device__ __align__(16) __nv_bfloat16 g_Al[128 * 8192];
__device__ __align__(16) __nv_bfloat16 g_Bh[128 * 8192];  // x_down_w hi [n][lm]
__device__ __align__(16) __nv_bfloat16 g_Bl[128 * 8192];
__device__ __align__(16) __nv_bfloat16 g_gWh[NOUT * KDIM];  // gamma*W hi [o][k]
__device__ __align__(16) __nv_bfloat16 g_gWl[NOUT * KDIM];
__device__ float g_cb[NOUT];
// normalized pair, bf16 hi/lo, [pair = i*256+l][k]  (128 MB each)
__device__ __align__(16) __nv_bfloat16 g_NpH[65536 * KDIM];
__device__ __align__(16) __nv_bfloat16 g_NpL[65536 * KDIM];

// ---------------- kernel A smem layout (bytes) ----------------
#define OFF_AH 0
#define OFF_AL 17408
#define OFF_BH 34816
#define OFF_BL 52224
#define OFF_NPH 0
#define OFF_NPL 33024
#define SMEM_A_TOTAL 69632

// ---------------- kernel B smem layout ----------------
#define BOFF_NH 0
#define BOFF_NL 16384
#define BOFF_GH 32768
#define BOFF_GL 49152
#define SMEM_B_TOTAL 65536

__device__ __forceinline__ uint32_t smem_u32(const void* p) {
    uint32_t a;
    asm("{ .reg .u64 t; cvta.to.shared.u64 t, %1; cvt.u32.u64 %0, t; }"
        : "=r"(a) : "l"(p));
    return a;
}
__device__ __forceinline__ void ldmx4t(uint32_t* r, uint32_t addr) {
    asm volatile("ldmatrix.sync.aligned.m8n8.x4.trans.shared.b16 {%0,%1,%2,%3}, [%4];"
                 : "=r"(r[0]), "=r"(r[1]), "=r"(r[2]), "=r"(r[3]) : "r"(addr));
}
__device__ __forceinline__ void ldmx2t(uint32_t* r, uint32_t addr) {
    asm volatile("ldmatrix.sync.aligned.m8n8.x2.trans.shared.b16 {%0,%1}, [%2];"
                 : "=r"(r[0]), "=r"(r[1]) : "r"(addr));
}
__device__ __forceinline__ void ldmx4(uint32_t* r, uint32_t addr) {
    asm volatile("ldmatrix.sync.aligned.m8n8.x4.shared.b16 {%0,%1,%2,%3}, [%4];"
                 : "=r"(r[0]), "=r"(r[1]), "=r"(r[2]), "=r"(r[3]) : "r"(addr));
}
__device__ __forceinline__ void mma16816(float* c, const uint32_t* a, const uint32_t* b) {
    asm volatile(
        "mma.sync.aligned.m16n8k16.row.col.f32.bf16.bf16.f32 "
        "{%0,%1,%2,%3}, {%4,%5,%6,%7}, {%8,%9}, {%0,%1,%2,%3};"
        : "+f"(c[0]), "+f"(c[1]), "+f"(c[2]), "+f"(c[3])
        : "r"(a[0]), "r"(a[1]), "r"(a[2]), "r"(a[3]), "r"(b[0]), "r"(b[1]));
}

// ---------------- prep (single kernel): fp32 -> bf16 hi/lo ----------------
__global__ void prep_all(const float* __restrict__ A, const float* __restrict__ B,
                         const float* __restrict__ gamma, const float* __restrict__ beta,
                         const float* __restrict__ W, const float* __restrict__ b) {
    if (blockIdx.x < 2048) {
        const unsigned v = blockIdx.x * 256 + threadIdx.x;  // 0..524287 (float4)
        const float4* src;
        __nv_bfloat16 *dh, *dl;
        unsigned i;
        if (v < 262144) { src = (const float4*)A; i = v; dh = g_Ah; dl = g_Al; }
        else            { src = (const float4*)B; i = v - 262144; dh = g_Bh; dl = g_Bl; }
        const float4 x = src[i];
        __nv_bfloat162 h01 = __floats2bfloat162_rn(x.x, x.y);
        __nv_bfloat162 h23 = __floats2bfloat162_rn(x.z, x.w);
        __nv_bfloat162 l01 = __floats2bfloat162_rn(x.x - __low2float(h01), x.y - __high2float(h01));
        __nv_bfloat162 l23 = __floats2bfloat162_rn(x.z - __low2float(h23), x.w - __high2float(h23));
        ((uint2*)dh)[i] = make_uint2(*(uint32_t*)&h01, *(uint32_t*)&h23);
        ((uint2*)dl)[i] = make_uint2(*(uint32_t*)&l01, *(uint32_t*)&l23);
    } else {
        const int o = blockIdx.x - 2048;   // 128 blocks
        const int t = threadIdx.x;
        float s = 0.f;
        for (int k = t; k < KDIM; k += 256) {
            const float wv = W[o * KDIM + k];
            const float gv = gamma[k] * wv;
            const __nv_bfloat16 h = __float2bfloat16(gv);
            g_gWh[o * KDIM + k] = h;
            g_gWl[o * KDIM + k] = __float2bfloat16(gv - __bfloat162float(h));
            s += beta[k] * wv;
        }
        __shared__ float red[256];
        red[t] = s;
        __syncthreads();
        for (int st = 128; st > 0; st >>= 1) {
            if (t < st) red[t] += red[t + st];
            __syncthreads();
        }
        if (t == 0) g_cb[o] = b[o] + red[0];
    }
}

// ---------------- kernel A: GEMM1 + LN -> g_Np hi/lo ----------------
__global__ __launch_bounds__(256, 2)
void coevol_g1_kernel() {
    extern __shared__ char sm[];
    const uint32_t SB = smem_u32(sm);

    const int tid = threadIdx.x;
    const int lane = tid & 31, w = tid >> 5;
    const int bx = blockIdx.x, by = blockIdx.y;

    const int mbase = (w & 3) * 32;     // ij tile base
    const int nbase = (w >> 2) * 64;    // lm tile base
    float acc[2][8][4];
#pragma unroll
    for (int mt = 0; mt < 2; ++mt)
#pragma unroll
        for (int nt = 0; nt < 8; ++nt)
#pragma unroll
            for (int c = 0; c < 4; ++c) acc[mt][nt][c] = 0.f;

    const int g4 = lane >> 3;
    const int grow = lane & 7;
    const int kadd4 = (g4 >> 1) * 8, madd4 = (g4 & 1) * 8;
    const int kadd2 = (g4 & 1) * 8;

    for (int nh = 0; nh < 2; ++nh) {
#pragma unroll
        for (int it = 0; it < 4; ++it) {
            const int v = it * 256 + tid;
            const int r = v >> 4, c = v & 15;
            const unsigned srcA = (unsigned)(nh * 64 + r) * 1024u + (unsigned)bx * 16u + c;
            const unsigned srcB = (unsigned)(nh * 64 + r) * 1024u + (unsigned)by * 16u + c;
            const unsigned dst = (unsigned)r * 272u + (unsigned)c * 16u;
            *(uint4*)(sm + OFF_AH + dst) = ((const uint4*)g_Ah)[srcA];
            *(uint4*)(sm + OFF_AL + dst) = ((const uint4*)g_Al)[srcA];
            *(uint4*)(sm + OFF_BH + dst) = ((const uint4*)g_Bh)[srcB];
            *(uint4*)(sm + OFF_BL + dst) = ((const uint4*)g_Bl)[srcB];
        }
        __syncthreads();

#pragma unroll
        for (int ks = 0; ks < 4; ++ks) {
            uint32_t ah[2][4], al[2][4];
#pragma unroll
            for (int mt = 0; mt < 2; ++mt) {
                const uint32_t aoff = (uint32_t)(ks * 16 + kadd4 + grow) * 272u
                                    + (uint32_t)(mbase + mt * 16 + madd4) * 2u;
                ldmx4t(ah[mt], SB + OFF_AH + aoff);
                ldmx4t(al[mt], SB + OFF_AL + aoff);
            }
#pragma unroll
            for (int nt = 0; nt < 8; ++nt) {
                uint32_t bh[2], bl[2];
                const uint32_t boff = (uint32_t)(ks * 16 + kadd2 + grow) * 272u
                                    + (uint32_t)(nbase + nt * 8) * 2u;
                ldmx2t(bh, SB + OFF_BH + boff);
                ldmx2t(bl, SB + OFF_BL + boff);
#pragma unroll
                for (int mt = 0; mt < 2; ++mt) {
                    mma16816(acc[mt][nt], ah[mt], bh);
                    mma16816(acc[mt][nt], ah[mt], bl);
                    mma16816(acc[mt][nt], al[mt], bh);
                }
            }
        }
        __syncthreads();
    }

    // ---------------- LayerNorm (warp-local) -> Np smem bf16 hi/lo ----------
    const int i_loc = w & 3;
#pragma unroll
    for (int lb = 0; lb < 2; ++lb) {
        const int l_loc = (w >> 2) * 2 + lb;
        float sum = 0.f, sq = 0.f;
#pragma unroll
        for (int mt = 0; mt < 2; ++mt)
#pragma unroll
            for (int nt4 = 0; nt4 < 4; ++nt4)
#pragma unroll
                for (int c = 0; c < 4; ++c) {
                    const float v = acc[mt][lb * 4 + nt4][c];
                    sum += v;
                    sq = fmaf(v, v, sq);
                }
#pragma unroll
        for (int off = 16; off >= 1; off >>= 1) {
            sum += __shfl_xor_sync(0xffffffffu, sum, off);
            sq  += __shfl_xor_sync(0xffffffffu, sq, off);
        }
        const float mean = sum * (1.f / KDIM);
        const float var  = sq * (1.f / KDIM) - mean * mean;
        const float rstd = rsqrtf(var + LN_EPS);
        const int p = i_loc * 4 + l_loc;
#pragma unroll
        for (int mt = 0; mt < 2; ++mt)
#pragma unroll
            for (int nt4 = 0; nt4 < 4; ++nt4)
#pragma unroll
                for (int cp = 0; cp < 2; ++cp) {
                    const float f0 = (acc[mt][lb * 4 + nt4][cp * 2 + 0] - mean) * rstd;
                    const float f1 = (acc[mt][lb * 4 + nt4][cp * 2 + 1] - mean) * rstd;
                    __nv_bfloat162 h2 = __floats2bfloat162_rn(f0, f1);
                    __nv_bfloat162 l2 = __floats2bfloat162_rn(f0 - __low2float(h2),
                                                              f1 - __high2float(h2));
                    const int j  = mt * 16 + (lane >> 2) + cp * 8;
                    const int mc = nt4 * 4 + (lane & 3);
                    const int idx = p * 516 + j * 16 + (mc ^ ((j & 3) << 2));
                    *(uint32_t*)(sm + OFF_NPH + idx * 4) = *(uint32_t*)&h2;
                    *(uint32_t*)(sm + OFF_NPL + idx * 4) = *(uint32_t*)&l2;
                }
    }
    __syncthreads();

    // ---------------- copy Np smem -> global (coalesced, unswizzled) --------
    // 16 p rows x 128 uint4 per row, hi + lo: 4096 uint4 total.
#pragma unroll
    for (int it = 0; it < 16; ++it) {
        const int v = it * 256 + tid;          // 0..4095
        const int arr = v >> 11;               // 0 = hi, 1 = lo
        const int rem = v & 2047;
        const int p = rem >> 7;                // 0..15
        const int c4 = rem & 127;              // uint4 within row
        const int wb = c4 * 4;                 // word index (bf16x2)
        const int j = wb >> 4, mc = wb & 15;   // mc is 4-aligned
        const int sidx = p * 516 + j * 16 + (mc ^ ((j & 3) << 2));
        const uint32_t* s = (const uint32_t*)(sm + (arr ? OFF_NPL : OFF_NPH)) + sidx;
        uint4 val = make_uint4(s[0], s[1], s[2], s[3]);
        const int gi = bx * 4 + (p >> 2);
        const int gl = by * 4 + (p & 3);
        const size_t pair = (size_t)gi * SEQ_L + gl;
        uint4* dst = (uint4*)(arr ? g_NpL : g_NpH) + pair * 128 + c4;
        *dst = val;
    }
}

// ---------------- kernel B: out[pair][o] = Np . gW + cb ----------------
// Grid 512: CTA = 128 pairs x 128 o, K = 1024 in 16 chunks of 64.
__global__ __launch_bounds__(256, 2)
void coevol_g2_kernel(float* __restrict__ out) {
    extern __shared__ char sm[];
    const uint32_t SB = smem_u32(sm);

    const int tid = threadIdx.x;
    const int lane = tid & 31, w = tid >> 5;
    const int pb = blockIdx.x;             // pair block (128 pairs)

    const int mp = (w & 3) * 32;           // warp pair-tile base (32 p)
    const int ob = (w >> 2) * 64;          // warp o-tile base (64 o)

    float acc[2][8][4];
#pragma unroll
    for (int mt = 0; mt < 2; ++mt)
#pragma unroll
        for (int nt = 0; nt < 8; ++nt)
#pragma unroll
            for (int c = 0; c < 4; ++c) acc[mt][nt][c] = 0.f;

    // ldmatrix lane addressing (non-trans)
    const int rA = lane & 15, cAs = lane >> 4;                    // A frag
    const int rB = ((lane >> 4) << 3) + (lane & 7);               // B frag
    const int cBs = (lane >> 3) & 1;

    for (int ch = 0; ch < 16; ++ch) {
        // stage 4 x [128 rows x 128 B] tiles (Np hi/lo rows=pair, gW hi/lo rows=o)
#pragma unroll
        for (int it = 0; it < 16; ++it) {
            const int v = it * 256 + tid;      // 0..4095 uint4
            const int buf = v >> 10;           // 0 NH, 1 NL, 2 GH, 3 GL
            const int rem = v & 1023;
            const int r = rem >> 3, c = rem & 7;
            uint4 val;
            if (buf == 0)
                val = ((const uint4*)g_NpH)[(size_t)(pb * 128 + r) * 128 + ch * 8 + c];
            else if (buf == 1)
                val = ((const uint4*)g_NpL)[(size_t)(pb * 128 + r) * 128 + ch * 8 + c];
            else if (buf == 2)
                val = ((const uint4*)g_gWh)[(size_t)r * 128 + ch * 8 + c];
            else
                val = ((const uint4*)g_gWl)[(size_t)r * 128 + ch * 8 + c];
            *(uint4*)(sm + buf * 16384 + r * 128 + ((c ^ (r & 7)) << 4)) = val;
        }
        __syncthreads();

#pragma unroll
        for (int ks = 0; ks < 4; ++ks) {
            const int cc = ks * 2;             // 16B-chunk base within 8
            uint32_t ah[2][4], al[2][4];
#pragma unroll
            for (int mt = 0; mt < 2; ++mt) {
                const int r = mp + mt * 16 + rA;
                const int c = cc + cAs;
                const uint32_t addr = SB + (uint32_t)(r * 128 + ((c ^ (r & 7)) << 4));
                ldmx4(ah[mt], addr + BOFF_NH);
                ldmx4(al[mt], addr + BOFF_NL);
            }
#pragma unroll
            for (int n4 = 0; n4 < 4; ++n4) {
                uint32_t bh[4], bl[4];
                const int r = ob + n4 * 16 + rB;
                const int c = cc + cBs;
                const uint32_t addr = SB + (uint32_t)(r * 128 + ((c ^ (r & 7)) << 4));
                ldmx4(bh, addr + BOFF_GH);
                ldmx4(bl, addr + BOFF_GL);
#pragma unroll
                for (int half = 0; half < 2; ++half) {
                    const int nt = n4 * 2 + half;
#pragma unroll
                    for (int mt = 0; mt < 2; ++mt) {
                        mma16816(acc[mt][nt], ah[mt], bh + half * 2);
                        mma16816(acc[mt][nt], ah[mt], bl + half * 2);
                        mma16816(acc[mt][nt], al[mt], bh + half * 2);
                    }
                }
            }
        }
        __syncthreads();
    }

    // ---------------- epilogue ----------------
#pragma unroll
    for (int nt = 0; nt < 8; ++nt) {
        const int o0 = ob + nt * 8 + 2 * (lane & 3);
        const float cb0 = g_cb[o0], cb1 = g_cb[o0 + 1];
#pragma unroll
        for (int mt = 0; mt < 2; ++mt) {
            const int r0 = mp + mt * 16 + (lane >> 2);
            const size_t pair0 = (size_t)pb * 128 + r0;
            float2 v0, v1;
            v0.x = acc[mt][nt][0] + cb0;
            v0.y = acc[mt][nt][1] + cb1;
            v1.x = acc[mt][nt][2] + cb0;
            v1.y = acc[mt][nt][3] + cb1;
            *(float2*)&out[pair0 * NOUT + o0] = v0;
            *(float2*)&out[(pair0 + 8) * NOUT + o0] = v1;
        }
    }
}

// ---------------------------------------------------------------------------
extern "C" void kernel_launch(void* const* d_in, const int* in_sizes, int n_in,
                              void* d_out, int out_size) {
    const float* x_down   = (const float*)d_in[0];
    const float* x_down_w = (const float*)d_in[1];
    const float* gamma    = (const float*)d_in[2];
    const float* beta     = (const float*)d_in[3];
    const float* W        = (const float*)d_in[4];
    const float* b        = (const float*)d_in[5];
    float* out = (float*)d_out;

    cudaFuncSetAttribute(coevol_g1_kernel,
                         cudaFuncAttributeMaxDynamicSharedMemorySize, SMEM_A_TOTAL);
    cudaFuncSetAttribute(coevol_g2_kernel,
                         cudaFuncAttributeMaxDynamicSharedMemorySize, SMEM_B_TOTAL);

    prep_all<<<2176, 256>>>(x_down, x_down_w, gamma, beta, W, b);

    dim3 grid1(SEQ_L / 4, SEQ_L / 4);  // 64 x 64
    coevol_g1_kernel<<<grid1, 256, SMEM_A_TOTAL>>>();

    coevol_g2_kernel<<<512, 256, SMEM_B_TOTAL>>>(out);
}

// round 9
// speedup vs baseline: 3.2441x; 1.0715x over previous
#include <cuda_runtime.h>
#include <cuda_bf16.h>
#include <cstdint>

#define LN_EPS 1e-5f
#define SEQ_L  256
#define KDIM   1024
#define NOUT   128

// ---------------- global scratch (no allocs allowed) ----------------
__device__ __align__(16) __nv_bfloat16 g_Ah[128 * 8192];  // x_down   hi [n][ij]
__device__ __align__(16) __nv_bfloat16 g_Al[128 * 8192];
__device__ __align__(16) __nv_bfloat16 g_Bh[128 * 8192];  // x_down_w hi [n][lm]
__device__ __align__(16) __nv_bfloat16 g_Bl[128 * 8192];
__device__ __align__(16) __nv_bfloat16 g_gWh[NOUT * KDIM];  // gamma*W hi [o][k]
__device__ __align__(16) __nv_bfloat16 g_gWl[NOUT * KDIM];
__device__ float g_cb[NOUT];
// normalized pair, bf16 hi/lo, [pair = i*256+l][k]
__device__ __align__(16) __nv_bfloat16 g_NpH[65536 * KDIM];
__device__ __align__(16) __nv_bfloat16 g_NpL[65536 * KDIM];

// ---------------- kernel A smem: 2 stages x (4 bufs x [32 n x 272 B]) ------
#define A_STAGE   34816
#define A_AH 0
#define A_AL 8704
#define A_BH 17408
#define A_BL 26112
#define OFF_NPH 0
#define OFF_NPL 33024
#define SMEM_A_TOTAL 69632

// ---------------- kernel B smem: 3 stages x (2 bufs x [128 r x 128 B]) -----
// row layout: bytes [0,64) = hi (k 0..31), [64,128) = lo
#define B_STAGE   32768
#define B_N 0
#define B_G 16384
#define SMEM_B_TOTAL 98304

__device__ __forceinline__ uint32_t smem_u32(const void* p) {
    uint32_t a;
    asm("{ .reg .u64 t; cvta.to.shared.u64 t, %1; cvt.u32.u64 %0, t; }"
        : "=r"(a) : "l"(p));
    return a;
}
__device__ __forceinline__ void cp16(uint32_t dst, const void* src) {
    asm volatile("cp.async.cg.shared.global [%0], [%1], 16;"
                 :: "r"(dst), "l"(src) : "memory");
}
__device__ __forceinline__ void cp_commit() {
    asm volatile("cp.async.commit_group;" ::: "memory");
}
template <int N> __device__ __forceinline__ void cp_wait() {
    asm volatile("cp.async.wait_group %0;" :: "n"(N) : "memory");
}
__device__ __forceinline__ void ldmx4t(uint32_t* r, uint32_t addr) {
    asm volatile("ldmatrix.sync.aligned.m8n8.x4.trans.shared.b16 {%0,%1,%2,%3}, [%4];"
                 : "=r"(r[0]), "=r"(r[1]), "=r"(r[2]), "=r"(r[3]) : "r"(addr));
}
__device__ __forceinline__ void ldmx2t(uint32_t* r, uint32_t addr) {
    asm volatile("ldmatrix.sync.aligned.m8n8.x2.trans.shared.b16 {%0,%1}, [%2];"
                 : "=r"(r[0]), "=r"(r[1]) : "r"(addr));
}
__device__ __forceinline__ void ldmx4(uint32_t* r, uint32_t addr) {
    asm volatile("ldmatrix.sync.aligned.m8n8.x4.shared.b16 {%0,%1,%2,%3}, [%4];"
                 : "=r"(r[0]), "=r"(r[1]), "=r"(r[2]), "=r"(r[3]) : "r"(addr));
}
__device__ __forceinline__ void mma16816(float* c, const uint32_t* a, const uint32_t* b) {
    asm volatile(
        "mma.sync.aligned.m16n8k16.row.col.f32.bf16.bf16.f32 "
        "{%0,%1,%2,%3}, {%4,%5,%6,%7}, {%8,%9}, {%0,%1,%2,%3};"
        : "+f"(c[0]), "+f"(c[1]), "+f"(c[2]), "+f"(c[3])
        : "r"(a[0]), "r"(a[1]), "r"(a[2]), "r"(a[3]), "r"(b[0]), "r"(b[1]));
}

// ---------------- prep: fp32 -> bf16 hi/lo ----------------
__global__ void prep_all(const float* __restrict__ A, const float* __restrict__ B,
                         const float* __restrict__ gamma, const float* __restrict__ beta,
                         const float* __restrict__ W, const float* __restrict__ b) {
    if (blockIdx.x < 2048) {
        const unsigned v = blockIdx.x * 256 + threadIdx.x;  // float4 index
        const float4* src;
        __nv_bfloat16 *dh, *dl;
        unsigned i;
        if (v < 262144) { src = (const float4*)A; i = v; dh = g_Ah; dl = g_Al; }
        else            { src = (const float4*)B; i = v - 262144; dh = g_Bh; dl = g_Bl; }
        const float4 x = src[i];
        __nv_bfloat162 h01 = __floats2bfloat162_rn(x.x, x.y);
        __nv_bfloat162 h23 = __floats2bfloat162_rn(x.z, x.w);
        __nv_bfloat162 l01 = __floats2bfloat162_rn(x.x - __low2float(h01), x.y - __high2float(h01));
        __nv_bfloat162 l23 = __floats2bfloat162_rn(x.z - __low2float(h23), x.w - __high2float(h23));
        ((uint2*)dh)[i] = make_uint2(*(uint32_t*)&h01, *(uint32_t*)&h23);
        ((uint2*)dl)[i] = make_uint2(*(uint32_t*)&l01, *(uint32_t*)&l23);
    } else {
        const int o = blockIdx.x - 2048;
        const int t = threadIdx.x;
        float s = 0.f;
        for (int k = t; k < KDIM; k += 256) {
            const float wv = W[o * KDIM + k];
            const float gv = gamma[k] * wv;
            const __nv_bfloat16 h = __float2bfloat16(gv);
            g_gWh[o * KDIM + k] = h;
            g_gWl[o * KDIM + k] = __float2bfloat16(gv - __bfloat162float(h));
            s += beta[k] * wv;
        }
        __shared__ float red[256];
        red[t] = s;
        __syncthreads();
        for (int st = 128; st > 0; st >>= 1) {
            if (t < st) red[t] += red[t + st];
            __syncthreads();
        }
        if (t == 0) g_cb[o] = b[o] + red[0];
    }
}

// ---------------- kernel A: GEMM1 + LN -> g_Np (2-stage cp.async) ----------
__global__ __launch_bounds__(256, 2)
void coevol_g1_kernel() {
    extern __shared__ char sm[];
    const uint32_t SB = smem_u32(sm);

    const int tid = threadIdx.x;
    const int lane = tid & 31, w = tid >> 5;
    const int bx = blockIdx.x, by = blockIdx.y;

    const int mbase = (w & 3) * 32;
    const int nbase = (w >> 2) * 64;
    float acc[2][8][4];
#pragma unroll
    for (int mt = 0; mt < 2; ++mt)
#pragma unroll
        for (int nt = 0; nt < 8; ++nt)
#pragma unroll
            for (int c = 0; c < 4; ++c) acc[mt][nt][c] = 0.f;

    const int g4 = lane >> 3;
    const int grow = lane & 7;
    const int kadd4 = (g4 >> 1) * 8, madd4 = (g4 & 1) * 8;
    const int kadd2 = (g4 & 1) * 8;

    // staging: 8 cp16 per thread per stage
    // v = t + it*256: buf = v>>9 (AH,AL,BH,BL); r = (v&511)>>4; c = v&15
    auto stage_load = [&](int ch) {
        const uint32_t stg = SB + (uint32_t)(ch & 1) * A_STAGE;
#pragma unroll
        for (int it = 0; it < 8; ++it) {
            const int v = it * 256 + tid;
            const int buf = v >> 9;
            const int rem = v & 511;
            const int r = rem >> 4, c = rem & 15;
            // g_A*/g_B* rows are 8192 bf16 = 16384 bytes per n
            const size_t srow = (size_t)(ch * 32 + r) * 16384;
            const uint32_t dst = stg + (uint32_t)buf * 8704u
                               + (uint32_t)r * 272u + (uint32_t)c * 16u;
            const char* src;
            if (buf == 0)      src = (const char*)g_Ah + srow + bx * 256 + c * 16;
            else if (buf == 1) src = (const char*)g_Al + srow + bx * 256 + c * 16;
            else if (buf == 2) src = (const char*)g_Bh + srow + by * 256 + c * 16;
            else               src = (const char*)g_Bl + srow + by * 256 + c * 16;
            cp16(dst, src);
        }
    };

    stage_load(0);
    cp_commit();

    for (int ch = 0; ch < 4; ++ch) {
        cp_wait<0>();
        __syncthreads();
        if (ch < 3) { stage_load(ch + 1); cp_commit(); }

        const uint32_t stg = SB + (uint32_t)(ch & 1) * A_STAGE;
#pragma unroll
        for (int ks = 0; ks < 2; ++ks) {
            uint32_t ah[2][4], al[2][4];
#pragma unroll
            for (int mt = 0; mt < 2; ++mt) {
                const uint32_t aoff = (uint32_t)(ks * 16 + kadd4 + grow) * 272u
                                    + (uint32_t)(mbase + mt * 16 + madd4) * 2u;
                ldmx4t(ah[mt], stg + A_AH + aoff);
                ldmx4t(al[mt], stg + A_AL + aoff);
            }
#pragma unroll
            for (int nt = 0; nt < 8; ++nt) {
                uint32_t bh[2], bl[2];
                const uint32_t boff = (uint32_t)(ks * 16 + kadd2 + grow) * 272u
                                    + (uint32_t)(nbase + nt * 8) * 2u;
                ldmx2t(bh, stg + A_BH + boff);
                ldmx2t(bl, stg + A_BL + boff);
#pragma unroll
                for (int mt = 0; mt < 2; ++mt) {
                    mma16816(acc[mt][nt], ah[mt], bh);
                    mma16816(acc[mt][nt], ah[mt], bl);
                    mma16816(acc[mt][nt], al[mt], bh);
                }
            }
        }
    }
    __syncthreads();  // all warps done with stage smem before LN store reuses it

    // ---------------- LayerNorm (warp-local) -> Np smem bf16 hi/lo ----------
    const int i_loc = w & 3;
#pragma unroll
    for (int lb = 0; lb < 2; ++lb) {
        const int l_loc = (w >> 2) * 2 + lb;
        float sum = 0.f, sq = 0.f;
#pragma unroll
        for (int mt = 0; mt < 2; ++mt)
#pragma unroll
            for (int nt4 = 0; nt4 < 4; ++nt4)
#pragma unroll
                for (int c = 0; c < 4; ++c) {
                    const float v = acc[mt][lb * 4 + nt4][c];
                    sum += v;
                    sq = fmaf(v, v, sq);
                }
#pragma unroll
        for (int off = 16; off >= 1; off >>= 1) {
            sum += __shfl_xor_sync(0xffffffffu, sum, off);
            sq  += __shfl_xor_sync(0xffffffffu, sq, off);
        }
        const float mean = sum * (1.f / KDIM);
        const float var  = sq * (1.f / KDIM) - mean * mean;
        const float rstd = rsqrtf(var + LN_EPS);
        const int p = i_loc * 4 + l_loc;
#pragma unroll
        for (int mt = 0; mt < 2; ++mt)
#pragma unroll
            for (int nt4 = 0; nt4 < 4; ++nt4)
#pragma unroll
                for (int cp = 0; cp < 2; ++cp) {
                    const float f0 = (acc[mt][lb * 4 + nt4][cp * 2 + 0] - mean) * rstd;
                    const float f1 = (acc[mt][lb * 4 + nt4][cp * 2 + 1] - mean) * rstd;
                    __nv_bfloat162 h2 = __floats2bfloat162_rn(f0, f1);
                    __nv_bfloat162 l2 = __floats2bfloat162_rn(f0 - __low2float(h2),
                                                              f1 - __high2float(h2));
                    const int j  = mt * 16 + (lane >> 2) + cp * 8;
                    const int mc = nt4 * 4 + (lane & 3);
                    const int idx = p * 516 + j * 16 + (mc ^ ((j & 3) << 2));
                    *(uint32_t*)(sm + OFF_NPH + idx * 4) = *(uint32_t*)&h2;
                    *(uint32_t*)(sm + OFF_NPL + idx * 4) = *(uint32_t*)&l2;
                }
    }
    __syncthreads();

    // ---------------- copy Np smem -> global (coalesced) ----------
#pragma unroll
    for (int it = 0; it < 16; ++it) {
        const int v = it * 256 + tid;          // 0..4095
        const int arr = v >> 11;
        const int rem = v & 2047;
        const int p = rem >> 7;
        const int c4 = rem & 127;
        const int wb = c4 * 4;
        const int j = wb >> 4, mc = wb & 15;
        const int sidx = p * 516 + j * 16 + (mc ^ ((j & 3) << 2));
        const uint32_t* s = (const uint32_t*)(sm + (arr ? OFF_NPL : OFF_NPH)) + sidx;
        uint4 val = make_uint4(s[0], s[1], s[2], s[3]);
        const int gi = bx * 4 + (p >> 2);
        const int gl = by * 4 + (p & 3);
        const size_t pair = (size_t)gi * SEQ_L + gl;
        uint4* dst = (uint4*)(arr ? g_NpL : g_NpH) + pair * 128 + c4;
        *dst = val;
    }
}

// ---------------- kernel B: out = Np . gW + cb (3-stage cp.async) ----------
// Grid 512: CTA = 128 pairs x 128 o, K = 1024 in 32 chunks of 32.
__global__ __launch_bounds__(256, 2)
void coevol_g2_kernel(float* __restrict__ out) {
    extern __shared__ char sm[];
    const uint32_t SB = smem_u32(sm);

    const int tid = threadIdx.x;
    const int lane = tid & 31, w = tid >> 5;
    const int pb = blockIdx.x;

    const int mp = (w & 3) * 32;
    const int ob = (w >> 2) * 64;

    float acc[2][8][4];
#pragma unroll
    for (int mt = 0; mt < 2; ++mt)
#pragma unroll
        for (int nt = 0; nt < 8; ++nt)
#pragma unroll
            for (int c = 0; c < 4; ++c) acc[mt][nt][c] = 0.f;

    const int rA = lane & 15, cAs = lane >> 4;
    const int rB = ((lane >> 4) << 3) + (lane & 7);
    const int cBs = (lane >> 3) & 1;

    // stage load: 8 cp16/thread. row layout: c<4 hi, c>=4 lo; xor-swizzled.
    auto stage_load = [&](int ch) {
        const uint32_t stg = SB + (uint32_t)(ch % 3) * B_STAGE;
#pragma unroll
        for (int it = 0; it < 8; ++it) {
            const int v = it * 256 + tid;
            const int buf = v >> 10;          // 0 = Np, 1 = gW
            const int rem = v & 1023;
            const int r = rem >> 3, c = rem & 7;
            const uint32_t dst = stg + (uint32_t)buf * 16384u
                               + (uint32_t)r * 128u
                               + (uint32_t)((c ^ (r & 7)) << 4);
            const char* src;
            if (buf == 0) {
                const size_t row = (size_t)(pb * 128 + r) * 2048;
                src = (c < 4)
                    ? (const char*)g_NpH + row + ch * 64 + c * 16
                    : (const char*)g_NpL + row + ch * 64 + (c - 4) * 16;
            } else {
                const size_t row = (size_t)r * 2048;
                src = (c < 4)
                    ? (const char*)g_gWh + row + ch * 64 + c * 16
                    : (const char*)g_gWl + row + ch * 64 + (c - 4) * 16;
            }
            cp16(dst, src);
        }
    };

    stage_load(0); cp_commit();
    stage_load(1); cp_commit();

    for (int ch = 0; ch < 32; ++ch) {
        if (ch < 31) cp_wait<1>(); else cp_wait<0>();
        __syncthreads();
        if (ch + 2 < 32) { stage_load(ch + 2); cp_commit(); }

        const uint32_t stg = SB + (uint32_t)(ch % 3) * B_STAGE;
#pragma unroll
        for (int ks = 0; ks < 2; ++ks) {
            const int cc = ks * 2;
            uint32_t ah[2][4], al[2][4];
#pragma unroll
            for (int mt = 0; mt < 2; ++mt) {
                const int r = mp + mt * 16 + rA;
                const int ch_ = cc + cAs;          // hi col 0..3
                const uint32_t base = stg + B_N + (uint32_t)(r * 128);
                ldmx4(ah[mt], base + (uint32_t)(((ch_) ^ (r & 7)) << 4));
                ldmx4(al[mt], base + (uint32_t)(((ch_ + 4) ^ (r & 7)) << 4));
            }
#pragma unroll
            for (int n4 = 0; n4 < 4; ++n4) {
                uint32_t bh[4], bl[4];
                const int r = ob + n4 * 16 + rB;
                const int ch_ = cc + cBs;
                const uint32_t base = stg + B_G + (uint32_t)(r * 128);
                ldmx4(bh, base + (uint32_t)(((ch_) ^ (r & 7)) << 4));
                ldmx4(bl, base + (uint32_t)(((ch_ + 4) ^ (r & 7)) << 4));
#pragma unroll
                for (int half = 0; half < 2; ++half) {
                    const int nt = n4 * 2 + half;
#pragma unroll
                    for (int mt = 0; mt < 2; ++mt) {
                        mma16816(acc[mt][nt], ah[mt], bh + half * 2);
                        mma16816(acc[mt][nt], ah[mt], bl + half * 2);
                        mma16816(acc[mt][nt], al[mt], bh + half * 2);
                    }
                }
            }
        }
    }

    // ---------------- epilogue ----------------
#pragma unroll
    for (int nt = 0; nt < 8; ++nt) {
        const int o0 = ob + nt * 8 + 2 * (lane & 3);
        const float cb0 = g_cb[o0], cb1 = g_cb[o0 + 1];
#pragma unroll
        for (int mt = 0; mt < 2; ++mt) {
            const int r0 = mp + mt * 16 + (lane >> 2);
            const size_t pair0 = (size_t)pb * 128 + r0;
            float2 v0, v1;
            v0.x = acc[mt][nt][0] + cb0;
            v0.y = acc[mt][nt][1] + cb1;
            v1.x = acc[mt][nt][2] + cb0;
            v1.y = acc[mt][nt][3] + cb1;
            *(float2*)&out[pair0 * NOUT + o0] = v0;
            *(float2*)&out[(pair0 + 8) * NOUT + o0] = v1;
        }
    }
}

// ---------------------------------------------------------------------------
extern "C" void kernel_launch(void* const* d_in, const int* in_sizes, int n_in,
                              void* d_out, int out_size) {
    const float* x_down   = (const float*)d_in[0];
    const float* x_down_w = (const float*)d_in[1];
    const float* gamma    = (const float*)d_in[2];
    const float* beta     = (const float*)d_in[3];
    const float* W        = (const float*)d_in[4];
    const float* b        = (const float*)d_in[5];
    float* out = (float*)d_out;

    cudaFuncSetAttribute(coevol_g1_kernel,
                         cudaFuncAttributeMaxDynamicSharedMemorySize, SMEM_A_TOTAL);
    cudaFuncSetAttribute(coevol_g2_kernel,
                         cudaFuncAttributeMaxDynamicSharedMemorySize, SMEM_B_TOTAL);

    prep_all<<<2176, 256>>>(x_down, x_down_w, gamma, beta, W, b);

    dim3 grid1(SEQ_L / 4, SEQ_L / 4);  // 64 x 64
    coevol_g1_kernel<<<grid1, 256, SMEM_A_TOTAL>>>();

    coevol_g2_kernel<<<512, 256, SMEM_B_TOTAL>>>(out);
}